// round 7
// baseline (speedup 1.0000x reference)
#include <cuda_runtime.h>
#include <cstdint>

// ---------------------------------------------------------------------------
// FanoCoupling, transposed-x layout + f32x2 packed over row pairs.
//
// Reduction: W = [W1 | W2], each 64x64.  8 unique half-matvecs:
//   A0=W1 x0, A1=W1 x1, A3=W1 x3, A4=W1 x4, B1=W2 x1, B2=W2 x2, B3=W2 x3, B5=W2 x5
// Combine:
//   out0=x0, out1=x1, out3=x3
//   out2 = x2 + g0*(A0+B1+b)
//   out4 = x4 + g1*(A0+B3+b)
//   out5 = x5 + g3*(A1+B3+b) + g6*(A4+B2+b)
//   out6 = x6 + g2*(A0+B5+b) + g4*(A4+B1+b) + g5*(A3+B2+b)
//
// smem: wT[f=64][z=128] (cols 0..63 = W1 z, 64..127 = W2 z), xT[c*64+f][row=32].
// Lane = rowgrp(0-7) x zgrp(0-3); thread = 4 rows x 2 z x 8 results.
// acc is fp32x2 over (even row, odd row):  x operand = natural LDS.128 from xT,
// w operand = mov.b64-replicated scalar, amortized over 4 rows.
// ---------------------------------------------------------------------------

#define ROW 448
#define TROWS 32
#define WT_FLOATS (64 * 128)
#define XT_FLOATS (7 * 64 * 32)
#define SMEM_FLOATS (WT_FLOATS + XT_FLOATS)

typedef unsigned long long ull;

__device__ __forceinline__ void fma2(ull &acc, ull a, ull b) {
    asm("fma.rn.f32x2 %0, %1, %2, %0;" : "+l"(acc) : "l"(a), "l"(b));
}
__device__ __forceinline__ ull rep2(float a) {
    ull r; asm("mov.b64 %0, {%1, %1};" : "=l"(r) : "f"(a)); return r;
}
__device__ __forceinline__ float accpart(ull a, int p) {
    return p ? __uint_as_float((unsigned)(a >> 32))
             : __uint_as_float((unsigned)(a & 0xffffffffULL));
}

__global__ __launch_bounds__(256, 2)
void fano_kernel(const float* __restrict__ x, const float* __restrict__ W,
                 const float* __restrict__ bias, const float* __restrict__ gates,
                 float* __restrict__ out, int nrows)
{
    extern __shared__ float smem[];
    float* wT = smem;               // [64][128]
    float* xT = smem + WT_FLOATS;   // [7*64][32]

    const int tid = threadIdx.x;
    const long long rowbase = (long long)blockIdx.x * TROWS;

    // ---- stage W with register 4x4 transpose (coalesced LDG, conflict-free STS)
    // items: zb4 (16 blocks of 4 z) x fb4 (32 blocks of 4 f over 0..127)
    for (int it = tid; it < 512; it += 256) {
        int zb4 = it & 15;
        int fb4 = it >> 4;
        float vv[4][4];
        #pragma unroll
        for (int j = 0; j < 4; j++) {
            float4 v = *reinterpret_cast<const float4*>(W + (zb4 * 4 + j) * 128 + fb4 * 4);
            vv[j][0] = v.x; vv[j][1] = v.y; vv[j][2] = v.z; vv[j][3] = v.w;
        }
        #pragma unroll
        for (int k = 0; k < 4; k++) {
            int f  = fb4 * 4 + k;
            int fp = (f < 64) ? f : f - 64;
            int zc = (f < 64) ? zb4 * 4 : 64 + zb4 * 4;
            float4 t = make_float4(vv[0][k], vv[1][k], vv[2][k], vv[3][k]);
            *reinterpret_cast<float4*>(wT + fp * 128 + zc) = t;
        }
    }

    // ---- stage xT with register 4x4 transpose
    // items: ((c*16 + fb)*8 + rg), rg fastest so STS phases are contiguous
    for (int it = tid; it < 896; it += 256) {
        int rg = it & 7;
        int cf = it >> 3;
        int fb = cf & 15;       // f block: f = 4*fb .. +3
        int c  = cf >> 4;       // 0..6
        float vv[4][4];
        #pragma unroll
        for (int j = 0; j < 4; j++) {
            long long row = rowbase + rg * 4 + j;
            float4 v = (row < nrows)
                ? *reinterpret_cast<const float4*>(x + row * ROW + c * 64 + fb * 4)
                : make_float4(0.f, 0.f, 0.f, 0.f);
            vv[j][0] = v.x; vv[j][1] = v.y; vv[j][2] = v.z; vv[j][3] = v.w;
        }
        #pragma unroll
        for (int k = 0; k < 4; k++) {
            float4 t = make_float4(vv[0][k], vv[1][k], vv[2][k], vv[3][k]);
            *reinterpret_cast<float4*>(xT + ((c * 64 + fb * 4 + k) << 5) + rg * 4) = t;
        }
    }
    __syncthreads();

    // ---- pass-through colonies 0,1,3: coalesced GMEM copy
    for (int i = tid; i < TROWS * 3 * 16; i += 256) {
        int r = i / 48, rem = i % 48;
        int ci = rem / 16, f4 = rem % 16;
        int c = (ci < 2) ? ci : 3;
        long long row = rowbase + r;
        if (row < nrows) {
            long long off = row * (long long)ROW + c * 64 + f4 * 4;
            *reinterpret_cast<float4*>(out + off) =
                *reinterpret_cast<const float4*>(x + off);
        }
    }

    // ---- main loop ---------------------------------------------------------
    const int lane = tid & 31, warp = tid >> 5;
    const int rg   = lane & 7;          // row group: rows rg*4 .. rg*4+3
    const int zgrp = lane >> 3;         // 0..3
    const int zb   = warp * 8 + zgrp * 2;   // thread's z pair: zb, zb+1

    ull acc[2][8][2];
    #pragma unroll
    for (int rp = 0; rp < 2; rp++)
        #pragma unroll
        for (int j = 0; j < 8; j++) { acc[rp][j][0] = 0ULL; acc[rp][j][1] = 0ULL; }

    const ulonglong2* xq = reinterpret_cast<const ulonglong2*>(xT) + rg;

    #pragma unroll 1
    for (int f = 0; f < 64; f++) {
        float2 w1 = *reinterpret_cast<const float2*>(wT + f * 128 + zb);
        float2 w2 = *reinterpret_cast<const float2*>(wT + f * 128 + 64 + zb);
        ull w1r0 = rep2(w1.x), w1r1 = rep2(w1.y);
        ull w2r0 = rep2(w2.x), w2r1 = rep2(w2.y);

        ulonglong2 xr0 = xq[(0 * 64 + f) * 8];
        ulonglong2 xr1 = xq[(1 * 64 + f) * 8];
        ulonglong2 xr2 = xq[(2 * 64 + f) * 8];
        ulonglong2 xr3 = xq[(3 * 64 + f) * 8];
        ulonglong2 xr4 = xq[(4 * 64 + f) * 8];
        ulonglong2 xr5 = xq[(5 * 64 + f) * 8];

        #pragma unroll
        for (int rp = 0; rp < 2; rp++) {
            ull x0 = rp ? xr0.y : xr0.x;
            ull x1 = rp ? xr1.y : xr1.x;
            ull x2 = rp ? xr2.y : xr2.x;
            ull x3 = rp ? xr3.y : xr3.x;
            ull x4 = rp ? xr4.y : xr4.x;
            ull x5 = rp ? xr5.y : xr5.x;
            fma2(acc[rp][0][0], x0, w1r0); fma2(acc[rp][0][1], x0, w1r1);  // A0
            fma2(acc[rp][1][0], x1, w1r0); fma2(acc[rp][1][1], x1, w1r1);  // A1
            fma2(acc[rp][2][0], x3, w1r0); fma2(acc[rp][2][1], x3, w1r1);  // A3
            fma2(acc[rp][3][0], x4, w1r0); fma2(acc[rp][3][1], x4, w1r1);  // A4
            fma2(acc[rp][4][0], x1, w2r0); fma2(acc[rp][4][1], x1, w2r1);  // B1
            fma2(acc[rp][5][0], x2, w2r0); fma2(acc[rp][5][1], x2, w2r1);  // B2
            fma2(acc[rp][6][0], x3, w2r0); fma2(acc[rp][6][1], x3, w2r1);  // B3
            fma2(acc[rp][7][0], x5, w2r0); fma2(acc[rp][7][1], x5, w2r1);  // B5
        }
    }

    // ---- gates softmax (tiny, per-thread) ----------------------------------
    float g[7];
    {
        float graw[7];
        #pragma unroll
        for (int i = 0; i < 7; i++) graw[i] = gates[i];
        float m = graw[0];
        #pragma unroll
        for (int i = 1; i < 7; i++) m = fmaxf(m, graw[i]);
        float s = 0.f;
        #pragma unroll
        for (int i = 0; i < 7; i++) { g[i] = expf(graw[i] - m); s += g[i]; }
        float inv = 1.f / s;
        #pragma unroll
        for (int i = 0; i < 7; i++) g[i] *= inv;
    }
    const float bz0 = bias[zb], bz1 = bias[zb + 1];

    // ---- epilogue: 4 rows x (z = zb, zb+1), computed colonies 2,4,5,6 ------
    #pragma unroll
    for (int rp = 0; rp < 2; rp++) {
        #pragma unroll
        for (int p = 0; p < 2; p++) {
            int rl = rg * 4 + rp * 2 + p;
            long long row = rowbase + rl;
            if (row >= nrows) continue;
            float* orow = out + row * (long long)ROW;

            float o2[2], o4[2], o5[2], o6[2];
            #pragma unroll
            for (int zg = 0; zg < 2; zg++) {
                float a0  = accpart(acc[rp][0][zg], p);
                float a1  = accpart(acc[rp][1][zg], p);
                float a3  = accpart(acc[rp][2][zg], p);
                float a4  = accpart(acc[rp][3][zg], p);
                float b1v = accpart(acc[rp][4][zg], p);
                float b2v = accpart(acc[rp][5][zg], p);
                float b3v = accpart(acc[rp][6][zg], p);
                float b5v = accpart(acc[rp][7][zg], p);
                float bz  = zg ? bz1 : bz0;
                int zz = zb + zg;
                float x2v = xT[((2 * 64 + zz) << 5) + rl];
                float x4v = xT[((4 * 64 + zz) << 5) + rl];
                float x5v = xT[((5 * 64 + zz) << 5) + rl];
                float x6v = xT[((6 * 64 + zz) << 5) + rl];
                o2[zg] = x2v + g[0] * (a0 + b1v + bz);
                o4[zg] = x4v + g[1] * (a0 + b3v + bz);
                o5[zg] = x5v + g[3] * (a1 + b3v + bz) + g[6] * (a4 + b2v + bz);
                o6[zg] = x6v + g[2] * (a0 + b5v + bz) + g[4] * (a4 + b1v + bz)
                             + g[5] * (a3 + b2v + bz);
            }
            *reinterpret_cast<float2*>(orow + 2 * 64 + zb) = make_float2(o2[0], o2[1]);
            *reinterpret_cast<float2*>(orow + 4 * 64 + zb) = make_float2(o4[0], o4[1]);
            *reinterpret_cast<float2*>(orow + 5 * 64 + zb) = make_float2(o5[0], o5[1]);
            *reinterpret_cast<float2*>(orow + 6 * 64 + zb) = make_float2(o6[0], o6[1]);
        }
    }
}

extern "C" void kernel_launch(void* const* d_in, const int* in_sizes, int n_in,
                              void* d_out, int out_size) {
    const float* x     = (const float*)d_in[0];   // colony_states [B,7,64]
    const float* W     = (const float*)d_in[1];   // [64,128]
    const float* bias  = (const float*)d_in[2];   // [64]
    const float* gates = (const float*)d_in[3];   // [7]
    float* out = (float*)d_out;

    int nrows = in_sizes[0] / ROW;
    int smem_bytes = SMEM_FLOATS * (int)sizeof(float);   // 90112 B
    cudaFuncSetAttribute(fano_kernel,
                         cudaFuncAttributeMaxDynamicSharedMemorySize, smem_bytes);
    int ctas = (nrows + TROWS - 1) / TROWS;
    fano_kernel<<<ctas, 256, smem_bytes>>>(x, W, bias, gates, out, nrows);
}

// round 8
// speedup vs baseline: 1.6195x; 1.6195x over previous
#include <cuda_runtime.h>
#include <cstdint>

// ---------------------------------------------------------------------------
// FanoCoupling: out = x + scatter-add over 7 Fano lines of softmax-gated
// Linear(concat(x_i, x_j)).
//
// Reduction: W = [W1 | W2], each 64x64.  8 unique half-matvecs:
//   A0=W1 x0, A1=W1 x1, A3=W1 x3, A4=W1 x4, B1=W2 x1, B2=W2 x2, B3=W2 x3, B5=W2 x5
// Combine:
//   out0=x0, out1=x1, out3=x3
//   out2 = x2 + g0*(A0+B1+b)
//   out4 = x4 + g1*(A0+B3+b)
//   out5 = x5 + g3*(A1+B3+b) + g6*(A4+B2+b)
//   out6 = x6 + g2*(A0+B5+b) + g4*(A4+B1+b) + g5*(A3+B2+b)
//
// R7 layout: lane = z, acc packed f32x2 over (z, z+32); ONE warp covers all
// 64 z.  Weights pre-paired (W[z][f],W[z+32][f]) by a pre-kernel so the weight
// load is a contiguous per-lane LDS.64 (2 wf).  x in natural [row][448]
// layout, uniform LDS.128 per (colony, 4f), replicated via mov.b64.
// Warp owns 4 rows; CTA = 8 warps = 32 rows; 2 CTAs/SM.
// ---------------------------------------------------------------------------

#define ROW 448
#define TROWS 32
#define WPS_ULL (128 * 33)                 // paired weights, stride 33 ull per f
#define SMEM_BYTES (WPS_ULL * 8 + TROWS * ROW * 4)   // 33792 + 57344 = 91136

typedef unsigned long long ull;

__device__ float wPg[16384];               // paired weights in GMEM scratch

__device__ __forceinline__ void fma2(ull &acc, ull a, ull b) {
    asm("fma.rn.f32x2 %0, %1, %2, %0;" : "+l"(acc) : "l"(a), "l"(b));
}
__device__ __forceinline__ ull add2(ull a, ull b) {
    ull r; asm("add.rn.f32x2 %0, %1, %2;" : "=l"(r) : "l"(a), "l"(b)); return r;
}
__device__ __forceinline__ ull rep2(float a) {
    ull r; asm("mov.b64 %0, {%1, %1};" : "=l"(r) : "f"(a)); return r;
}
__device__ __forceinline__ ull pack2(float lo, float hi) {
    ull r; asm("mov.b64 %0, {%1, %2};" : "=l"(r) : "f"(lo), "f"(hi)); return r;
}
__device__ __forceinline__ void unpack2(float &lo, float &hi, ull a) {
    asm("mov.b64 {%0, %1}, %2;" : "=f"(lo), "=f"(hi) : "l"(a));
}

// Pre-kernel: pair weights (W[z][f], W[z+32][f]) -> wPg[((half*64+fc)*32+zlo)*2+slot]
__global__ void pack_w(const float* __restrict__ W) {
    int i = blockIdx.x * 256 + threadIdx.x;
    if (i < 8192) {
        int z = i >> 7, f = i & 127;
        float v = W[i];
        int half = f >> 6, fc = f & 63, zlo = z & 31, slot = z >> 5;
        wPg[(((half << 6) + fc) << 6) + (zlo << 1) + slot] = v;
    }
}

__global__ __launch_bounds__(256, 2)
void fano_kernel(const float* __restrict__ x, const float* __restrict__ bias,
                 const float* __restrict__ gates, float* __restrict__ out,
                 int nrows)
{
    extern __shared__ char smem_raw[];
    ull*   wPs = reinterpret_cast<ull*>(smem_raw);                 // [128][33]
    float* xs  = reinterpret_cast<float*>(smem_raw + WPS_ULL * 8); // [32][448]

    const int tid = threadIdx.x;
    const long long rowbase = (long long)blockIdx.x * TROWS;

    // --- stage paired weights (coalesced LDG.64, near-contiguous STS) ------
    {
        const ull* wg = reinterpret_cast<const ull*>(wPg);
        for (int i = tid; i < 4096; i += 256) {
            int fc = i >> 5, zl = i & 31;
            wPs[fc * 33 + zl] = wg[i];
        }
    }

    // --- stage x tile, natural layout (float4 coalesced) -------------------
    {
        int tile_rows = (nrows - rowbase < TROWS) ? (int)(nrows - rowbase) : TROWS;
        int tile_e4 = tile_rows * (ROW / 4);
        const float4* gx = reinterpret_cast<const float4*>(x + rowbase * ROW);
        float4* sx = reinterpret_cast<float4*>(xs);
        for (int i = tid; i < tile_e4; i += 256) sx[i] = gx[i];
        if (tile_rows < TROWS)
            for (int i = tid + tile_e4; i < TROWS * (ROW / 4); i += 256)
                sx[i] = make_float4(0.f, 0.f, 0.f, 0.f);
    }
    __syncthreads();

    // --- pass-through colonies 0,1,3 (coalesced smem->gmem copy) -----------
    for (int i = tid; i < TROWS * 3 * 16; i += 256) {
        int r = i / 48, rem = i % 48;
        int ci = rem / 16, f4 = rem % 16;
        int c = (ci < 2) ? ci : 3;
        long long row = rowbase + r;
        if (row < nrows) {
            *reinterpret_cast<float4*>(out + row * (long long)ROW + c * 64 + f4 * 4) =
                *reinterpret_cast<const float4*>(xs + r * ROW + c * 64 + f4 * 4);
        }
    }

    const int warp = tid >> 5, lane = tid & 31;

    // acc[r][res], res: 0=A0 1=A1 2=A3 3=A4 4=B1 5=B2 6=B3 7=B5
    // packed f32x2: lo = z=lane, hi = z=lane+32
    ull acc[4][8];
    #pragma unroll
    for (int r = 0; r < 4; r++)
        #pragma unroll
        for (int j = 0; j < 8; j++) acc[r][j] = 0ULL;

    const ull* w1p = wPs + lane;           // + f*33
    const ull* w2p = wPs + 64 * 33 + lane;

    #pragma unroll 1
    for (int fb = 0; fb < 16; fb++) {      // f = 4*fb .. 4*fb+3
        ull w1[4], w2[4];
        #pragma unroll
        for (int k = 0; k < 4; k++) {
            w1[k] = w1p[(fb * 4 + k) * 33];
            w2[k] = w2p[(fb * 4 + k) * 33];
        }
        #pragma unroll
        for (int r = 0; r < 4; r++) {
            const float* xr = xs + (warp * 4 + r) * ROW + fb * 4;
            float4 v; ull e;
            v = *reinterpret_cast<const float4*>(xr + 0 * 64);     // c0 -> A0
            #pragma unroll
            for (int k = 0; k < 4; k++) {
                e = rep2(reinterpret_cast<const float*>(&v)[k]);
                fma2(acc[r][0], w1[k], e);
            }
            v = *reinterpret_cast<const float4*>(xr + 1 * 64);     // c1 -> A1,B1
            #pragma unroll
            for (int k = 0; k < 4; k++) {
                e = rep2(reinterpret_cast<const float*>(&v)[k]);
                fma2(acc[r][1], w1[k], e); fma2(acc[r][4], w2[k], e);
            }
            v = *reinterpret_cast<const float4*>(xr + 2 * 64);     // c2 -> B2
            #pragma unroll
            for (int k = 0; k < 4; k++) {
                e = rep2(reinterpret_cast<const float*>(&v)[k]);
                fma2(acc[r][5], w2[k], e);
            }
            v = *reinterpret_cast<const float4*>(xr + 3 * 64);     // c3 -> A3,B3
            #pragma unroll
            for (int k = 0; k < 4; k++) {
                e = rep2(reinterpret_cast<const float*>(&v)[k]);
                fma2(acc[r][2], w1[k], e); fma2(acc[r][6], w2[k], e);
            }
            v = *reinterpret_cast<const float4*>(xr + 4 * 64);     // c4 -> A4
            #pragma unroll
            for (int k = 0; k < 4; k++) {
                e = rep2(reinterpret_cast<const float*>(&v)[k]);
                fma2(acc[r][3], w1[k], e);
            }
            v = *reinterpret_cast<const float4*>(xr + 5 * 64);     // c5 -> B5
            #pragma unroll
            for (int k = 0; k < 4; k++) {
                e = rep2(reinterpret_cast<const float*>(&v)[k]);
                fma2(acc[r][7], w2[k], e);
            }
        }
    }

    // --- gates softmax (tiny, per-thread) ----------------------------------
    ull gr[7];
    {
        float graw[7], g[7];
        #pragma unroll
        for (int i = 0; i < 7; i++) graw[i] = gates[i];
        float m = graw[0];
        #pragma unroll
        for (int i = 1; i < 7; i++) m = fmaxf(m, graw[i]);
        float s = 0.f;
        #pragma unroll
        for (int i = 0; i < 7; i++) { g[i] = expf(graw[i] - m); s += g[i]; }
        float inv = 1.f / s;
        #pragma unroll
        for (int i = 0; i < 7; i++) gr[i] = rep2(g[i] * inv);
    }
    const ull bP = pack2(bias[lane], bias[lane + 32]);

    // --- epilogue: computed colonies 2,4,5,6; packed math, coalesced STG.32 -
    #pragma unroll
    for (int r = 0; r < 4; r++) {
        long long row = rowbase + warp * 4 + r;
        if (row >= nrows) break;
        float* orow = out + row * (long long)ROW;
        const float* xrow = xs + (warp * 4 + r) * ROW;

        ull x2P = pack2(xrow[2 * 64 + lane], xrow[2 * 64 + lane + 32]);
        ull x4P = pack2(xrow[4 * 64 + lane], xrow[4 * 64 + lane + 32]);
        ull x5P = pack2(xrow[5 * 64 + lane], xrow[5 * 64 + lane + 32]);
        ull x6P = pack2(xrow[6 * 64 + lane], xrow[6 * 64 + lane + 32]);

        ull t, o;
        float lo, hi;
        // out2 = x2 + g0*(A0+B1+b)
        o = x2P; t = add2(add2(acc[r][0], acc[r][4]), bP); fma2(o, t, gr[0]);
        unpack2(lo, hi, o);
        orow[2 * 64 + lane] = lo; orow[2 * 64 + lane + 32] = hi;
        // out4 = x4 + g1*(A0+B3+b)
        o = x4P; t = add2(add2(acc[r][0], acc[r][6]), bP); fma2(o, t, gr[1]);
        unpack2(lo, hi, o);
        orow[4 * 64 + lane] = lo; orow[4 * 64 + lane + 32] = hi;
        // out5 = x5 + g3*(A1+B3+b) + g6*(A4+B2+b)
        o = x5P;
        t = add2(add2(acc[r][1], acc[r][6]), bP); fma2(o, t, gr[3]);
        t = add2(add2(acc[r][3], acc[r][5]), bP); fma2(o, t, gr[6]);
        unpack2(lo, hi, o);
        orow[5 * 64 + lane] = lo; orow[5 * 64 + lane + 32] = hi;
        // out6 = x6 + g2*(A0+B5+b) + g4*(A4+B1+b) + g5*(A3+B2+b)
        o = x6P;
        t = add2(add2(acc[r][0], acc[r][7]), bP); fma2(o, t, gr[2]);
        t = add2(add2(acc[r][3], acc[r][4]), bP); fma2(o, t, gr[4]);
        t = add2(add2(acc[r][2], acc[r][5]), bP); fma2(o, t, gr[5]);
        unpack2(lo, hi, o);
        orow[6 * 64 + lane] = lo; orow[6 * 64 + lane + 32] = hi;
    }
}

extern "C" void kernel_launch(void* const* d_in, const int* in_sizes, int n_in,
                              void* d_out, int out_size) {
    const float* x     = (const float*)d_in[0];   // colony_states [B,7,64]
    const float* W     = (const float*)d_in[1];   // [64,128]
    const float* bias  = (const float*)d_in[2];   // [64]
    const float* gates = (const float*)d_in[3];   // [7]
    float* out = (float*)d_out;

    int nrows = in_sizes[0] / ROW;
    pack_w<<<32, 256>>>(W);
    cudaFuncSetAttribute(fano_kernel,
                         cudaFuncAttributeMaxDynamicSharedMemorySize, SMEM_BYTES);
    int ctas = (nrows + TROWS - 1) / TROWS;
    fano_kernel<<<ctas, 256, SMEM_BYTES>>>(x, bias, gates, out, nrows);
}